// round 15
// baseline (speedup 1.0000x reference)
#include <cuda_runtime.h>
#include <cuda_bf16.h>
#include <math.h>
#include <stdint.h>

#define BSZ 256
#define HSZ 256
#define TIN 336
#define TOUT 96
#define FSZ 32
#define PH 128
#define PX 16
#define NCTA 128
#define NTHR 512
#define SMW 57344

__device__ uint32_t g_h0hi[2][BSZ * PH], g_h0lo[2][BSZ * PH];
__device__ uint32_t g_h1hi[2][BSZ * PH], g_h1lo[2][BSZ * PH];
__device__ uint32_t g_xhi[BSZ * TIN * PX], g_xlo[BSZ * TIN * PX];
__device__ float g_Wp[4 * HSZ * HSZ], g_bp[4 * HSZ];
__device__ float g_h1s[(size_t)TOUT * BSZ * HSZ];
__device__ unsigned g_gbar[8 * 32];

__device__ uint32_t g_eWih0h[1024 * 16],  g_eWih0l[1024 * 16];
__device__ uint32_t g_eWhh0h[1024 * 128], g_eWhh0l[1024 * 128];
__device__ uint32_t g_eWih1h[1024 * 128], g_eWih1l[1024 * 128];
__device__ uint32_t g_eWhh1h[1024 * 128], g_eWhh1l[1024 * 128];
__device__ uint32_t g_dWih0h[1024 * 16],  g_dWih0l[1024 * 16];
__device__ uint32_t g_dWhh0h[1024 * 128], g_dWhh0l[1024 * 128];
__device__ uint32_t g_dWih1h[1024 * 128], g_dWih1l[1024 * 128];
__device__ uint32_t g_dWhh1h[1024 * 128], g_dWhh1l[1024 * 128];
__device__ uint32_t g_Wph[1024 * 128],    g_Wpl[1024 * 128];

__device__ __forceinline__ int j2lp(int j) { return ((j & 1) << 2) | (j >> 1); }

__device__ __forceinline__ void split2(float v0, float v1, uint32_t& hi, uint32_t& lo) {
  __nv_bfloat16 h0 = __float2bfloat16_rn(v0), h1 = __float2bfloat16_rn(v1);
  __nv_bfloat16 l0 = __float2bfloat16_rn(v0 - __bfloat162float(h0));
  __nv_bfloat16 l1 = __float2bfloat16_rn(v1 - __bfloat162float(h1));
  __nv_bfloat162 ph = __nv_bfloat162(h0, h1), pl = __nv_bfloat162(l0, l1);
  hi = *(uint32_t*)&ph;
  lo = *(uint32_t*)&pl;
}

#define MMA_BF16(C, a0, a1, a2, a3, b0, b1)                                   \
  asm volatile(                                                               \
      "mma.sync.aligned.m16n8k16.row.col.f32.bf16.bf16.f32 "                  \
      "{%0,%1,%2,%3},{%4,%5,%6,%7},{%8,%9},{%0,%1,%2,%3};"                    \
      : "+f"(C[0]), "+f"(C[1]), "+f"(C[2]), "+f"(C[3])                        \
      : "r"(a0), "r"(a1), "r"(a2), "r"(a3), "r"(b0), "r"(b1))

#define LDG_CG2(v, p)                                                         \
  asm volatile("ld.global.cg.v2.u32 {%0,%1},[%2];"                            \
               : "=r"((v).x), "=r"((v).y) : "l"(p))

// ---------------- init / preprocess ----------------
__global__ void zero_init_kernel() {
  int i = blockIdx.x * blockDim.x + threadIdx.x;
  g_h0hi[0][i] = 0u; g_h0lo[0][i] = 0u;
  g_h1hi[0][i] = 0u; g_h1lo[0][i] = 0u;
  if (i < 256) g_gbar[i] = 0u;
}

__global__ void wp_kernel(const float* __restrict__ Wih0, const float* __restrict__ Wout) {
  __shared__ float wr[FSZ];
  int c = blockIdx.x;
  if (threadIdx.x < FSZ) wr[threadIdx.x] = Wih0[c * FSZ + threadIdx.x];
  __syncthreads();
  int k = threadIdx.x;
  float acc = 0.f;
#pragma unroll
  for (int f = 0; f < FSZ; ++f) acc += wr[f] * Wout[f * HSZ + k];
  g_Wp[c * HSZ + k] = acc;
}

__global__ void bp_kernel(const float* __restrict__ Wih0, const float* __restrict__ b0,
                          const float* __restrict__ bout) {
  int c = blockIdx.x * blockDim.x + threadIdx.x;
  float acc = b0[c];
#pragma unroll
  for (int f = 0; f < FSZ; ++f) acc += Wih0[c * FSZ + f] * bout[f];
  g_bp[c] = acc;
}

__device__ __forceinline__ void pack_one(const float* W, int K, int li,
                                         uint32_t* ohi, uint32_t* olo) {
  int P = K >> 1;
  int pr = li / P, w = li % P;
  int n = pr & 63, by = pr >> 6;
  int eps = (n >> 3) & 1, qq = (n >> 1) & 3, dlt = n & 1;
  int gate = 2 * eps + dlt;
  int hid = ((n >> 4) << 2) + qq;
  int r = gate * 256 + by * 16 + hid;
  int cch = w >> 3, j = w & 7;
  int k0 = cch * 16 + 2 * j2lp(j);
  split2(W[r * K + k0], W[r * K + k0 + 1], ohi[li], olo[li]);
}

// all 9 weight packs in ONE launch (keeps lstm_persist at launch #6 for ncu -s 5)
__global__ void pack_all(const float* eWih0, const float* eWhh0,
                         const float* eWih1, const float* eWhh1,
                         const float* dWih0, const float* dWhh0,
                         const float* dWih1, const float* dWhh1) {
  int idx = blockIdx.x * 256 + threadIdx.x;
  if (idx < 16384) { pack_one(eWih0, 32, idx, g_eWih0h, g_eWih0l); return; }
  if (idx < 32768) { pack_one(dWih0, 32, idx - 16384, g_dWih0h, g_dWih0l); return; }
  int r = idx - 32768;
  int job = r >> 17, li = r & 131071;
  switch (job) {
    case 0: pack_one(eWhh0, 256, li, g_eWhh0h, g_eWhh0l); break;
    case 1: pack_one(eWih1, 256, li, g_eWih1h, g_eWih1l); break;
    case 2: pack_one(eWhh1, 256, li, g_eWhh1h, g_eWhh1l); break;
    case 3: pack_one(dWhh0, 256, li, g_dWhh0h, g_dWhh0l); break;
    case 4: pack_one(dWih1, 256, li, g_dWih1h, g_dWih1l); break;
    case 5: pack_one(dWhh1, 256, li, g_dWhh1h, g_dWhh1l); break;
    default: pack_one(g_Wp, 256, li, g_Wph, g_Wpl); break;
  }
}

__global__ void pack_x(const float* __restrict__ x) {
  int idx = blockIdx.x * 256 + threadIdx.x;
  int w = idx & (PX - 1), bt = idx >> 4;
  int cch = w >> 3, j = w & 7;
  int k0 = cch * 16 + 2 * j2lp(j);
  const float* src = x + (size_t)bt * FSZ + k0;
  split2(src[0], src[1], g_xhi[idx], g_xlo[idx]);
}

// ---------------- persistent building blocks ----------------
__device__ __forceinline__ void garrive(int grp) {
  __threadfence();
  __syncthreads();
  if (threadIdx.x == 0) atomicAdd(&g_gbar[grp * 32], 1u);
}

__device__ __forceinline__ void gwait(int grp, unsigned target) {
  if (threadIdx.x == 0) {
    volatile unsigned* p = &g_gbar[grp * 32];
    while (*p < target) {}
  }
  __syncthreads();
}

__device__ __forceinline__ void ld_res(uint32_t* dst, const uint32_t* src,
                                       int P, int by, int tid) {
  const uint32_t* s = src + (size_t)(by * 64) * P;
  for (int idx = tid * 2; idx < 64 * P; idx += 1024) {
    int rw = idx / P, w = idx - rw * P;
    int c = w >> 3, j = w & 7;
    uint2 v = *(const uint2*)(s + (size_t)rw * P + w);
    *(uint2*)&dst[c * 512 + rw * 8 + j] = v;
  }
}

template <int GC, bool SW>
__device__ __forceinline__ void ld_grp(uint2* rA, uint2* rW,
    const uint32_t* __restrict__ ahi, const uint32_t* __restrict__ alo,
    int lda, const uint32_t* __restrict__ gwl, int row0, int tid) {
  constexpr int ITS = (GC + 3) / 4;
#pragma unroll
  for (int it = 0; it < ITS; ++it) {
    int idx = tid * 2 + it * 1024;
    if (GC >= 4 || idx < GC * 256) {
      int rw = (idx & 255) >> 3, j = idx & 7, c = idx >> 8;
      size_t go = (size_t)(row0 + rw) * lda + (c << 3) + j;
      LDG_CG2(rA[2 * it], ahi + go);
      LDG_CG2(rA[2 * it + 1], alo + go);
    }
  }
  if (SW) {
#pragma unroll
    for (int it = 0; it < (GC + 1) / 2; ++it) {
      int idx = tid * 2 + it * 1024;
      int rw = (idx & 511) >> 3, j = idx & 7, c = idx >> 9;
      LDG_CG2(rW[it], gwl + rw * PH + (c << 3) + j);
    }
  }
}

template <int GC, bool SW>
__device__ __forceinline__ void st_grp(const uint2* rA, const uint2* rW,
                                       uint32_t* sA, uint32_t* sWst, int tid) {
  constexpr int ITS = (GC + 3) / 4;
#pragma unroll
  for (int it = 0; it < ITS; ++it) {
    int idx = tid * 2 + it * 1024;
    if (GC >= 4 || idx < GC * 256) {
      *(uint2*)&sA[idx] = rA[2 * it];
      *(uint2*)&sA[2048 + idx] = rA[2 * it + 1];
    }
  }
  if (SW) {
#pragma unroll
    for (int it = 0; it < (GC + 1) / 2; ++it)
      *(uint2*)&sWst[tid * 2 + it * 1024] = rW[it];
  }
}

template <int GC>
__device__ __forceinline__ void comp_grp(float* a0, float* a1,
    const uint32_t* sA, const uint32_t* swh, const uint32_t* swl,
    int aoff, int boff0, int boff1, int ks) {
  int cb = ks * (GC >> 1);
#pragma unroll
  for (int ci = 0; ci < (GC >> 1); ++ci) {
    int c = cb + ci;
    const uint32_t* bAh = sA + (c << 8);
    const uint32_t* bAl = bAh + 2048;
    const uint32_t* bWh = swh + (c << 9);
    const uint32_t* bWl = swl + (c << 9);
    uint2 Ah0 = *(const uint2*)(bAh + aoff), Ah1 = *(const uint2*)(bAh + aoff + 64);
    uint2 Al0 = *(const uint2*)(bAl + aoff), Al1 = *(const uint2*)(bAl + aoff + 64);
    uint2 Bh0 = *(const uint2*)(bWh + boff0), Bl0 = *(const uint2*)(bWl + boff0);
    uint2 Bh1 = *(const uint2*)(bWh + boff1), Bl1 = *(const uint2*)(bWl + boff1);
    MMA_BF16(a0, Ah0.x, Ah1.x, Ah0.y, Ah1.y, Bh0.x, Bh0.y);
    MMA_BF16(a0, Ah0.x, Ah1.x, Ah0.y, Ah1.y, Bl0.x, Bl0.y);
    MMA_BF16(a0, Al0.x, Al1.x, Al0.y, Al1.y, Bh0.x, Bh0.y);
    MMA_BF16(a1, Ah0.x, Ah1.x, Ah0.y, Ah1.y, Bh1.x, Bh1.y);
    MMA_BF16(a1, Ah0.x, Ah1.x, Ah0.y, Ah1.y, Bl1.x, Bl1.y);
    MMA_BF16(a1, Al0.x, Al1.x, Al0.y, Al1.y, Bh1.x, Bh1.y);
  }
}

__device__ __forceinline__ void epilogue(
    float* a0, float* a1, float* creg, float4 bu,
    int row0, int by, int tid, int ks, int wm, int g_, int hidT,
    uint32_t* __restrict__ outHi, uint32_t* __restrict__ outLo,
    float* __restrict__ outF, float* sbase) {
  float* psum = sbase;
  float* hbuf = sbase + 2048;
  __syncthreads();
  if (ks) {
    float4* p = (float4*)(psum + (tid - 256) * 8);
    p[0] = make_float4(a0[0], a0[1], a0[2], a0[3]);
    p[1] = make_float4(a1[0], a1[1], a1[2], a1[3]);
  }
  __syncthreads();
  if (!ks) {
    const float4* p = (const float4*)(psum + tid * 8);
    float4 p0 = p[0], p1 = p[1];
    a0[0] += p0.x; a0[1] += p0.y; a0[2] += p0.z; a0[3] += p0.w;
    a1[0] += p1.x; a1[1] += p1.y; a1[2] += p1.z; a1[3] += p1.w;
#pragma unroll
    for (int uu = 0; uu < 2; ++uu) {
      int row = wm + g_ + 8 * uu;
      float gi = (uu ? a0[2] : a0[0]) + bu.x;
      float gf = (uu ? a0[3] : a0[1]) + bu.y;
      float gg = (uu ? a1[2] : a1[0]) + bu.z;
      float go = (uu ? a1[3] : a1[1]) + bu.w;
      float si = 1.f / (1.f + expf(-gi));
      float sf = 1.f / (1.f + expf(-gf));
      float so = 1.f / (1.f + expf(-go));
      float cn = sf * creg[uu] + si * tanhf(gg);
      float hn = so * tanhf(cn);
      creg[uu] = cn;
      hbuf[row * 17 + hidT] = hn;
      if (outF) outF[(size_t)(row0 + row) * HSZ + by * 16 + hidT] = hn;
    }
  }
  __syncthreads();
  if (tid < 256) {
    int pr = tid >> 3, jj = tid & 7, lp = j2lp(jj);
    uint32_t hi, lo;
    split2(hbuf[pr * 17 + 2 * lp], hbuf[pr * 17 + 2 * lp + 1], hi, lo);
    size_t o = (size_t)(row0 + pr) * PH + by * 8 + jj;
    outHi[o] = hi;
    outLo[o] = lo;
  }
}

__device__ __forceinline__ float4 bias4(const float* b, int gh) {
  return make_float4(b[gh], b[HSZ + gh], b[2 * HSZ + gh], b[3 * HSZ + gh]);
}

#define SYNC_ST(GC, SW)                                                       \
  __syncthreads();                                                            \
  st_grp<GC, SW>(rA, rW, sA, sWst, tid);                                      \
  __syncthreads()

// ---------------- persistent kernel (split arrive/wait barriers) ----------------
__global__ __launch_bounds__(NTHR) void lstm_persist(
    const float* __restrict__ eb0, const float* __restrict__ eb1,
    const float* __restrict__ db0, const float* __restrict__ db1) {
  extern __shared__ uint32_t smem[];
  int tid = threadIdx.x;
  int bx = blockIdx.x & 7, by = blockIdx.x >> 3;
  int row0 = bx * 32;
  int lane = tid & 31, wid = tid >> 5, g_ = lane >> 2, q = lane & 3;
  int ks = wid >> 3, wpos = wid & 7;
  int wm = (wpos & 1) * 16, wn = (wpos >> 1) * 16;
  int hidT = (wn >> 2) + q;
  int aoff = (wm + g_) * 8 + 2 * q;
  int boff0 = (wn + g_) * 8 + 2 * q, boff1 = (wn + 8 + g_) * 8 + 2 * q;
  uint32_t* sA = smem + 49152;
  uint32_t* sWst = smem + 53248;
  float* sbase = (float*)sA;
  int gh = by * 16 + hidT;
  float c0r[2] = {0.f, 0.f}, c1r[2] = {0.f, 0.f};
  unsigned evt = 0;
  int par = 0;
  uint2 rA[4], rW[4];

  // ---- encoder ----
  ld_res(smem + 0,     g_eWhh0h, 128, by, tid);
  ld_res(smem + 8192,  g_eWhh0l, 128, by, tid);
  ld_res(smem + 16384, g_eWih1h, 128, by, tid);
  ld_res(smem + 24576, g_eWih1l, 128, by, tid);
  ld_res(smem + 32768, g_eWhh1h, 128, by, tid);
  ld_res(smem + 40960, g_eWhh1l, 128, by, tid);
  ld_res(sWst,         g_eWih0h, 16, by, tid);
  ld_res(sWst + 1024,  g_eWih0l, 16, by, tid);
  float4 be0 = bias4(eb0, gh), be1 = bias4(eb1, gh);

  for (int t = 0; t < TIN; ++t) {
    const uint32_t *h0h = g_h0hi[par], *h0l = g_h0lo[par];
    const uint32_t *h1h = g_h1hi[par], *h1l = g_h1lo[par];
    {  // L0a: h0old @ Whh0 (covered by wait#1(t-1)); hides wait#2(t-1)
      float a0[4] = {}, a1[4] = {};
      ld_grp<8, false>(rA, rW, h0h, h0l, PH, 0, row0, tid);
      SYNC_ST(8, false);
      ld_grp<8, false>(rA, rW, h0h + 64, h0l + 64, PH, 0, row0, tid);
      comp_grp<8>(a0, a1, sA, smem + 0, smem + 8192, aoff, boff0, boff1, ks);
      SYNC_ST(8, false);
      ld_grp<2, false>(rA, rW, g_xhi + (size_t)t * PX, g_xlo + (size_t)t * PX,
                       TIN * PX, 0, row0, tid);
      comp_grp<8>(a0, a1, sA, smem + 4096, smem + 12288, aoff, boff0, boff1, ks);
      if (t) gwait(bx, evt * 16);       // E2(t-1): h1(t-1) visible
      // L0b: x @ Wih0, epilogue
      SYNC_ST(2, false);
      comp_grp<2>(a0, a1, sA, sWst, sWst + 1024, aoff, boff0, boff1, ks);
      epilogue(a0, a1, c0r, be0, row0, by, tid, ks, wm, g_, hidT,
               g_h0hi[par ^ 1], g_h0lo[par ^ 1], nullptr, sbase);
      evt++; garrive(bx);               // E1(t)
    }
    {  // L1a: h1old @ Whh1 (covered by wait#2(t-1)); hides wait#1(t)
      float d0[4] = {}, d1[4] = {};
      ld_grp<8, false>(rA, rW, h1h, h1l, PH, 0, row0, tid);
      SYNC_ST(8, false);
      ld_grp<8, false>(rA, rW, h1h + 64, h1l + 64, PH, 0, row0, tid);
      comp_grp<8>(d0, d1, sA, smem + 32768, smem + 40960, aoff, boff0, boff1, ks);
      SYNC_ST(8, false);
      comp_grp<8>(d0, d1, sA, smem + 36864, smem + 45056, aoff, boff0, boff1, ks);
      gwait(bx, evt * 16);              // E1(t): h0new visible
      // L1b: h0new @ Wih1, epilogue
      const uint32_t *nh = g_h0hi[par ^ 1], *nl = g_h0lo[par ^ 1];
      ld_grp<8, false>(rA, rW, nh, nl, PH, 0, row0, tid);
      SYNC_ST(8, false);
      ld_grp<8, false>(rA, rW, nh + 64, nl + 64, PH, 0, row0, tid);
      comp_grp<8>(d0, d1, sA, smem + 16384, smem + 24576, aoff, boff0, boff1, ks);
      SYNC_ST(8, false);
      comp_grp<8>(d0, d1, sA, smem + 20480, smem + 28672, aoff, boff0, boff1, ks);
      epilogue(d0, d1, c1r, be1, row0, by, tid, ks, wm, g_, hidT,
               g_h1hi[par ^ 1], g_h1lo[par ^ 1], nullptr, sbase);
      evt++; garrive(bx);               // E2(t)
    }
    par ^= 1;
  }

  // ---- decoder: reload resident weights (overlaps E2 skew) ----
  ld_res(smem + 0,     g_Wph,    128, by, tid);
  ld_res(smem + 8192,  g_Wpl,    128, by, tid);
  ld_res(smem + 16384, g_dWhh0h, 128, by, tid);
  ld_res(smem + 24576, g_dWhh0l, 128, by, tid);
  ld_res(smem + 32768, g_dWih1h, 128, by, tid);
  ld_res(smem + 40960, g_dWhh1h, 128, by, tid);
  ld_res(sWst,         g_dWih0h, 16, by, tid);
  ld_res(sWst + 1024,  g_dWih0l, 16, by, tid);
  __syncthreads();
  const uint32_t* ih1lo = g_dWih1l + (size_t)by * 64 * PH;
  const uint32_t* hh1lo = g_dWhh1l + (size_t)by * 64 * PH;
  float4 bd0 = bias4(db0, gh), bdp = bias4(g_bp, gh), bd1 = bias4(db1, gh);

  for (int s = 0; s < TOUT; ++s) {
    const uint32_t *h0h = g_h0hi[par], *h0l = g_h0lo[par];
    const uint32_t *h1h = g_h1hi[par], *h1l = g_h1lo[par];
    {  // L0a: h0old @ Whh0 (covered by D1(s-1)/E1); hides wait D2(s-1)/E2
      float a0[4] = {}, a1[4] = {};
      ld_grp<8, false>(rA, rW, h0h, h0l, PH, 0, row0, tid);
      SYNC_ST(8, false);
      ld_grp<8, false>(rA, rW, h0h + 64, h0l + 64, PH, 0, row0, tid);
      comp_grp<8>(a0, a1, sA, smem + 16384, smem + 24576, aoff, boff0, boff1, ks);
      SYNC_ST(8, false);
      comp_grp<8>(a0, a1, sA, smem + 20480, smem + 28672, aoff, boff0, boff1, ks);
      gwait(bx, evt * 16);              // h1old visible
      // L0b
      if (s == 0) {
        ld_grp<2, false>(rA, rW, g_xhi + (size_t)(TIN - 1) * PX,
                         g_xlo + (size_t)(TIN - 1) * PX, TIN * PX, 0, row0, tid);
        SYNC_ST(2, false);
        comp_grp<2>(a0, a1, sA, sWst, sWst + 1024, aoff, boff0, boff1, ks);
        epilogue(a0, a1, c0r, bd0, row0, by, tid, ks, wm, g_, hidT,
                 g_h0hi[par ^ 1], g_h0lo[par ^ 1], nullptr, sbase);
      } else {  // h1old @ Wp
        ld_grp<8, false>(rA, rW, h1h, h1l, PH, 0, row0, tid);
        SYNC_ST(8, false);
        ld_grp<8, false>(rA, rW, h1h + 64, h1l + 64, PH, 0, row0, tid);
        comp_grp<8>(a0, a1, sA, smem + 0, smem + 8192, aoff, boff0, boff1, ks);
        SYNC_ST(8, false);
        comp_grp<8>(a0, a1, sA, smem + 4096, smem + 12288, aoff, boff0, boff1, ks);
        epilogue(a0, a1, c0r, bdp, row0, by, tid, ks, wm, g_, hidT,
                 g_h0hi[par ^ 1], g_h0lo[par ^ 1], nullptr, sbase);
      }
      evt++; garrive(bx);               // D1(s)
    }
    {  // L1a: h1old @ Whh1 (lo streamed); hides wait D1(s)
      float d0[4] = {}, d1[4] = {};
      ld_grp<8, true>(rA, rW, h1h, h1l, PH, hh1lo, row0, tid);
      SYNC_ST(8, true);
      ld_grp<8, true>(rA, rW, h1h + 64, h1l + 64, PH, hh1lo + 64, row0, tid);
      comp_grp<8>(d0, d1, sA, smem + 40960, sWst, aoff, boff0, boff1, ks);
      SYNC_ST(8, true);
      comp_grp<8>(d0, d1, sA, smem + 45056, sWst, aoff, boff0, boff1, ks);
      gwait(bx, evt * 16);              // h0new visible
      // L1b: h0new @ Wih1 (lo streamed)
      const uint32_t *nh = g_h0hi[par ^ 1], *nl = g_h0lo[par ^ 1];
      ld_grp<8, true>(rA, rW, nh, nl, PH, ih1lo, row0, tid);
      SYNC_ST(8, true);
      ld_grp<8, true>(rA, rW, nh + 64, nl + 64, PH, ih1lo + 64, row0, tid);
      comp_grp<8>(d0, d1, sA, smem + 32768, sWst, aoff, boff0, boff1, ks);
      SYNC_ST(8, true);
      comp_grp<8>(d0, d1, sA, smem + 36864, sWst, aoff, boff0, boff1, ks);
      epilogue(d0, d1, c1r, bd1, row0, by, tid, ks, wm, g_, hidT,
               g_h1hi[par ^ 1], g_h1lo[par ^ 1],
               g_h1s + (size_t)s * BSZ * HSZ, sbase);
      evt++; garrive(bx);               // D2(s)
    }
    par ^= 1;
  }
}

// ---------------- final projection ----------------
__global__ __launch_bounds__(256) void out_proj(const float* __restrict__ Wout,
                                                const float* __restrict__ bout,
                                                float* __restrict__ out) {
  __shared__ float hs[32][65];
  __shared__ float wsT[64][36];
  int tid = threadIdx.x;
  int b0 = blockIdx.x * 32, s = blockIdx.y;
  int bloc = tid & 31, f0 = (tid >> 5) * 4;
  float acc[4] = {0.f, 0.f, 0.f, 0.f};
  const float* hsrc = g_h1s + (size_t)s * BSZ * HSZ;
  for (int k0 = 0; k0 < HSZ; k0 += 64) {
    __syncthreads();
#pragma unroll
    for (int qq = 0; qq < 2; ++qq) {
      int idx = tid + qq * 256, row = idx >> 4, kq = idx & 15;
      float4 v = *(const float4*)(hsrc + (size_t)(b0 + row) * HSZ + k0 + kq * 4);
      hs[row][kq * 4 + 0] = v.x; hs[row][kq * 4 + 1] = v.y;
      hs[row][kq * 4 + 2] = v.z; hs[row][kq * 4 + 3] = v.w;
      float4 w = *(const float4*)(Wout + (size_t)row * HSZ + k0 + kq * 4);
      wsT[kq * 4 + 0][row] = w.x; wsT[kq * 4 + 1][row] = w.y;
      wsT[kq * 4 + 2][row] = w.z; wsT[kq * 4 + 3][row] = w.w;
    }
    __syncthreads();
#pragma unroll 8
    for (int kk = 0; kk < 64; ++kk) {
      float hv = hs[bloc][kk];
      float4 w = *(const float4*)&wsT[kk][f0];
      acc[0] += hv * w.x; acc[1] += hv * w.y;
      acc[2] += hv * w.z; acc[3] += hv * w.w;
    }
  }
  float* op = out + (size_t)(b0 + bloc) * TOUT * FSZ + s * FSZ + f0;
  op[0] = acc[0] + bout[f0 + 0];
  op[1] = acc[1] + bout[f0 + 1];
  op[2] = acc[2] + bout[f0 + 2];
  op[3] = acc[3] + bout[f0 + 3];
}

// ---------------- host ----------------
extern "C" void kernel_launch(void* const* d_in, const int* in_sizes, int n_in,
                              void* d_out, int out_size) {
  (void)in_sizes; (void)n_in; (void)out_size;
  const float* x     = (const float*)d_in[0];
  const float* eWih0 = (const float*)d_in[1];
  const float* eWhh0 = (const float*)d_in[2];
  const float* eb0   = (const float*)d_in[3];
  const float* eWih1 = (const float*)d_in[4];
  const float* eWhh1 = (const float*)d_in[5];
  const float* eb1   = (const float*)d_in[6];
  const float* dWih0 = (const float*)d_in[7];
  const float* dWhh0 = (const float*)d_in[8];
  const float* db0   = (const float*)d_in[9];
  const float* dWih1 = (const float*)d_in[10];
  const float* dWhh1 = (const float*)d_in[11];
  const float* db1   = (const float*)d_in[12];
  const float* dWout = (const float*)d_in[13];
  const float* dbout = (const float*)d_in[14];

  cudaFuncSetAttribute(lstm_persist, cudaFuncAttributeMaxDynamicSharedMemorySize,
                       SMW * 4);

  // launch order matters for ncu (-s 5 -c 1 captures launch #6 = lstm_persist)
  zero_init_kernel<<<(BSZ * PH) / 256, 256>>>();                       // 1
  wp_kernel<<<4 * HSZ, 256>>>(dWih0, dWout);                           // 2
  bp_kernel<<<(4 * HSZ) / 256, 256>>>(dWih0, db0, dbout);              // 3
  pack_x<<<(BSZ * TIN * PX) / 256, 256>>>(x);                          // 4
  pack_all<<<3712, 256>>>(eWih0, eWhh0, eWih1, eWhh1,                  // 5
                          dWih0, dWhh0, dWih1, dWhh1);
  lstm_persist<<<NCTA, NTHR, SMW * 4>>>(eb0, eb1, db0, db1);           // 6
  out_proj<<<dim3(BSZ / 32, TOUT), 256>>>(dWout, dbout, (float*)d_out);// 7
}

// round 16
// speedup vs baseline: 1.3389x; 1.3389x over previous
#include <cuda_runtime.h>
#include <cuda_bf16.h>
#include <math.h>
#include <stdint.h>

#define BSZ 256
#define HSZ 256
#define TIN 336
#define TOUT 96
#define FSZ 32
#define PH 128
#define PX 16
#define NCTA 128
#define NTHR 512
#define SMW 57344

__device__ uint32_t g_h0hi[2][BSZ * PH];
__device__ uint32_t g_h1hi[2][BSZ * PH];
__device__ uint32_t g_xhi[BSZ * TIN * PX];
__device__ float g_Wp[4 * HSZ * HSZ], g_bp[4 * HSZ];
__device__ float g_h1s[(size_t)TOUT * BSZ * HSZ];
__device__ unsigned g_gbar[8 * 32];

__device__ uint32_t g_eWih0h[1024 * 16],  g_eWih0l[1024 * 16];
__device__ uint32_t g_eWhh0h[1024 * 128], g_eWhh0l[1024 * 128];
__device__ uint32_t g_eWih1h[1024 * 128], g_eWih1l[1024 * 128];
__device__ uint32_t g_eWhh1h[1024 * 128], g_eWhh1l[1024 * 128];
__device__ uint32_t g_dWih0h[1024 * 16],  g_dWih0l[1024 * 16];
__device__ uint32_t g_dWhh0h[1024 * 128], g_dWhh0l[1024 * 128];
__device__ uint32_t g_dWih1h[1024 * 128], g_dWih1l[1024 * 128];
__device__ uint32_t g_dWhh1h[1024 * 128], g_dWhh1l[1024 * 128];
__device__ uint32_t g_Wph[1024 * 128],    g_Wpl[1024 * 128];

__device__ __forceinline__ int j2lp(int j) { return ((j & 1) << 2) | (j >> 1); }

__device__ __forceinline__ void split2(float v0, float v1, uint32_t& hi, uint32_t& lo) {
  __nv_bfloat16 h0 = __float2bfloat16_rn(v0), h1 = __float2bfloat16_rn(v1);
  __nv_bfloat16 l0 = __float2bfloat16_rn(v0 - __bfloat162float(h0));
  __nv_bfloat16 l1 = __float2bfloat16_rn(v1 - __bfloat162float(h1));
  __nv_bfloat162 ph = __nv_bfloat162(h0, h1), pl = __nv_bfloat162(l0, l1);
  hi = *(uint32_t*)&ph;
  lo = *(uint32_t*)&pl;
}

__device__ __forceinline__ uint32_t pack2(float v0, float v1) {
  __nv_bfloat162 ph = __nv_bfloat162(__float2bfloat16_rn(v0), __float2bfloat16_rn(v1));
  return *(uint32_t*)&ph;
}

#define MMA_BF16(C, a0, a1, a2, a3, b0, b1)                                   \
  asm volatile(                                                               \
      "mma.sync.aligned.m16n8k16.row.col.f32.bf16.bf16.f32 "                  \
      "{%0,%1,%2,%3},{%4,%5,%6,%7},{%8,%9},{%0,%1,%2,%3};"                    \
      : "+f"(C[0]), "+f"(C[1]), "+f"(C[2]), "+f"(C[3])                        \
      : "r"(a0), "r"(a1), "r"(a2), "r"(a3), "r"(b0), "r"(b1))

#define LDG_CG2(v, p)                                                         \
  asm volatile("ld.global.cg.v2.u32 {%0,%1},[%2];"                            \
               : "=r"((v).x), "=r"((v).y) : "l"(p))

// ---------------- init / preprocess ----------------
__global__ void zero_init_kernel() {
  int i = blockIdx.x * blockDim.x + threadIdx.x;
  g_h0hi[0][i] = 0u;
  g_h1hi[0][i] = 0u;
  if (i < 256) g_gbar[i] = 0u;
}

__global__ void wp_kernel(const float* __restrict__ Wih0, const float* __restrict__ Wout) {
  __shared__ float wr[FSZ];
  int c = blockIdx.x;
  if (threadIdx.x < FSZ) wr[threadIdx.x] = Wih0[c * FSZ + threadIdx.x];
  __syncthreads();
  int k = threadIdx.x;
  float acc = 0.f;
#pragma unroll
  for (int f = 0; f < FSZ; ++f) acc += wr[f] * Wout[f * HSZ + k];
  g_Wp[c * HSZ + k] = acc;
}

__global__ void bp_kernel(const float* __restrict__ Wih0, const float* __restrict__ b0,
                          const float* __restrict__ bout) {
  int c = blockIdx.x * blockDim.x + threadIdx.x;
  float acc = b0[c];
#pragma unroll
  for (int f = 0; f < FSZ; ++f) acc += Wih0[c * FSZ + f] * bout[f];
  g_bp[c] = acc;
}

// gate-interleaved packing (each mma thread's accumulators = {i,f,g,o} of one hid)
__global__ void pack_w(const float* __restrict__ W, int K,
                       uint32_t* __restrict__ ohi, uint32_t* __restrict__ olo) {
  int P = K >> 1;
  int idx = blockIdx.x * 256 + threadIdx.x;
  if (idx >= 1024 * P) return;
  int pr = idx / P, w = idx % P;
  int n = pr & 63, by = pr >> 6;
  int eps = (n >> 3) & 1, qq = (n >> 1) & 3, dlt = n & 1;
  int gate = 2 * eps + dlt;
  int hid = ((n >> 4) << 2) + qq;
  int r = gate * 256 + by * 16 + hid;
  int cch = w >> 3, j = w & 7;
  int k0 = cch * 16 + 2 * j2lp(j);
  split2(W[r * K + k0], W[r * K + k0 + 1], ohi[idx], olo[idx]);
}

__global__ void pack_x(const float* __restrict__ x) {
  int idx = blockIdx.x * 256 + threadIdx.x;
  int w = idx & (PX - 1), bt = idx >> 4;
  int cch = w >> 3, j = w & 7;
  int k0 = cch * 16 + 2 * j2lp(j);
  const float* src = x + (size_t)bt * FSZ + k0;
  g_xhi[idx] = pack2(src[0], src[1]);
}

// ---------------- persistent building blocks ----------------
__device__ __forceinline__ void gbar(int grp, unsigned target) {
  __syncthreads();
  __threadfence();
  if (threadIdx.x == 0) {
    unsigned old = atomicAdd(&g_gbar[grp * 32], 1u);
    if (old + 1u < target) {
      volatile unsigned* p = &g_gbar[grp * 32];
      while (*p < target) {}
    }
  }
  __syncthreads();
}

__device__ __forceinline__ void ld_res(uint32_t* dst, const uint32_t* src,
                                       int P, int by, int tid) {
  const uint32_t* s = src + (size_t)(by * 64) * P;
  for (int idx = tid * 2; idx < 64 * P; idx += 1024) {
    int rw = idx / P, w = idx - rw * P;
    int c = w >> 3, j = w & 7;
    uint2 v = *(const uint2*)(s + (size_t)rw * P + w);
    *(uint2*)&dst[c * 512 + rw * 8 + j] = v;
  }
}

// A (bf16 hi only) + optional streamed W-lo prefetch into registers
template <int GC, bool SW>
__device__ __forceinline__ void ld_grp(uint2* rA, uint2* rW,
    const uint32_t* __restrict__ ahi, int lda,
    const uint32_t* __restrict__ gwl, int row0, int tid) {
  constexpr int ITS = (GC + 3) / 4;
#pragma unroll
  for (int it = 0; it < ITS; ++it) {
    int idx = tid * 2 + it * 1024;
    if (GC >= 4 || idx < GC * 256) {
      int rw = (idx & 255) >> 3, j = idx & 7, c = idx >> 8;
      size_t go = (size_t)(row0 + rw) * lda + (c << 3) + j;
      LDG_CG2(rA[it], ahi + go);
    }
  }
  if (SW) {
#pragma unroll
    for (int it = 0; it < (GC + 1) / 2; ++it) {
      int idx = tid * 2 + it * 1024;
      int rw = (idx & 511) >> 3, j = idx & 7, c = idx >> 9;
      LDG_CG2(rW[it], gwl + rw * PH + (c << 3) + j);
    }
  }
}

template <int GC, bool SW>
__device__ __forceinline__ void st_grp(const uint2* rA, const uint2* rW,
                                       uint32_t* sA, uint32_t* sWst, int tid) {
  constexpr int ITS = (GC + 3) / 4;
#pragma unroll
  for (int it = 0; it < ITS; ++it) {
    int idx = tid * 2 + it * 1024;
    if (GC >= 4 || idx < GC * 256) *(uint2*)&sA[idx] = rA[it];
  }
  if (SW) {
#pragma unroll
    for (int it = 0; it < (GC + 1) / 2; ++it)
      *(uint2*)&sWst[tid * 2 + it * 1024] = rW[it];
  }
}

// bf16x2: A-hi x (W-hi + W-lo) -> 4 MMAs per chunk-position
template <int GC>
__device__ __forceinline__ void comp_grp(float* a0, float* a1,
    const uint32_t* sA, const uint32_t* swh, const uint32_t* swl,
    int aoff, int boff0, int boff1, int ks) {
  int cb = ks * (GC >> 1);
#pragma unroll
  for (int ci = 0; ci < (GC >> 1); ++ci) {
    int c = cb + ci;
    const uint32_t* bAh = sA + (c << 8);
    const uint32_t* bWh = swh + (c << 9);
    const uint32_t* bWl = swl + (c << 9);
    uint2 Ah0 = *(const uint2*)(bAh + aoff), Ah1 = *(const uint2*)(bAh + aoff + 64);
    uint2 Bh0 = *(const uint2*)(bWh + boff0), Bl0 = *(const uint2*)(bWl + boff0);
    uint2 Bh1 = *(const uint2*)(bWh + boff1), Bl1 = *(const uint2*)(bWl + boff1);
    MMA_BF16(a0, Ah0.x, Ah1.x, Ah0.y, Ah1.y, Bh0.x, Bh0.y);
    MMA_BF16(a0, Ah0.x, Ah1.x, Ah0.y, Ah1.y, Bl0.x, Bl0.y);
    MMA_BF16(a1, Ah0.x, Ah1.x, Ah0.y, Ah1.y, Bh1.x, Bh1.y);
    MMA_BF16(a1, Ah0.x, Ah1.x, Ah0.y, Ah1.y, Bl1.x, Bl1.y);
  }
}

// k-split reduce + register-resident pointwise; h packed as plain bf16 pairs
__device__ __forceinline__ void epilogue(
    float* a0, float* a1, float* creg, float4 bu,
    int row0, int by, int tid, int ks, int wm, int g_, int hidT,
    uint32_t* __restrict__ outHi, float* __restrict__ outF, float* sbase) {
  float* psum = sbase;
  float* hbuf = sbase + 2048;
  __syncthreads();
  if (ks) {
    float4* p = (float4*)(psum + (tid - 256) * 8);
    p[0] = make_float4(a0[0], a0[1], a0[2], a0[3]);
    p[1] = make_float4(a1[0], a1[1], a1[2], a1[3]);
  }
  __syncthreads();
  if (!ks) {
    const float4* p = (const float4*)(psum + tid * 8);
    float4 p0 = p[0], p1 = p[1];
    a0[0] += p0.x; a0[1] += p0.y; a0[2] += p0.z; a0[3] += p0.w;
    a1[0] += p1.x; a1[1] += p1.y; a1[2] += p1.z; a1[3] += p1.w;
#pragma unroll
    for (int uu = 0; uu < 2; ++uu) {
      int row = wm + g_ + 8 * uu;
      float gi = (uu ? a0[2] : a0[0]) + bu.x;
      float gf = (uu ? a0[3] : a0[1]) + bu.y;
      float gg = (uu ? a1[2] : a1[0]) + bu.z;
      float go = (uu ? a1[3] : a1[1]) + bu.w;
      float si = 1.f / (1.f + expf(-gi));
      float sf = 1.f / (1.f + expf(-gf));
      float so = 1.f / (1.f + expf(-go));
      float cn = sf * creg[uu] + si * tanhf(gg);
      float hn = so * tanhf(cn);
      creg[uu] = cn;
      hbuf[row * 17 + hidT] = hn;
      if (outF) outF[(size_t)(row0 + row) * HSZ + by * 16 + hidT] = hn;
    }
  }
  __syncthreads();
  if (tid < 256) {
    int pr = tid >> 3, jj = tid & 7, lp = j2lp(jj);
    size_t o = (size_t)(row0 + pr) * PH + by * 8 + jj;
    outHi[o] = pack2(hbuf[pr * 17 + 2 * lp], hbuf[pr * 17 + 2 * lp + 1]);
  }
}

__device__ __forceinline__ float4 bias4(const float* b, int gh) {
  return make_float4(b[gh], b[HSZ + gh], b[2 * HSZ + gh], b[3 * HSZ + gh]);
}

#define SYNC_ST(GC, SW)                                                       \
  __syncthreads();                                                            \
  st_grp<GC, SW>(rA, rW, sA, sWst, tid);                                      \
  __syncthreads()

// ---------------- persistent kernel ----------------
__global__ __launch_bounds__(NTHR) void lstm_persist(
    const float* __restrict__ eb0, const float* __restrict__ eb1,
    const float* __restrict__ db0, const float* __restrict__ db1) {
  extern __shared__ uint32_t smem[];
  int tid = threadIdx.x;
  int bx = blockIdx.x & 7, by = blockIdx.x >> 3;
  int row0 = bx * 32;
  int lane = tid & 31, wid = tid >> 5, g_ = lane >> 2, q = lane & 3;
  int ks = wid >> 3, wpos = wid & 7;
  int wm = (wpos & 1) * 16, wn = (wpos >> 1) * 16;
  int hidT = (wn >> 2) + q;
  int aoff = (wm + g_) * 8 + 2 * q;
  int boff0 = (wn + g_) * 8 + 2 * q, boff1 = (wn + 8 + g_) * 8 + 2 * q;
  uint32_t* sA = smem + 49152;
  uint32_t* sWst = smem + 53248;
  float* sbase = (float*)sA;
  int gh = by * 16 + hidT;
  float c0r[2] = {0.f, 0.f}, c1r[2] = {0.f, 0.f};
  unsigned bt = 0;
  int par = 0;
  uint2 rA[2], rW[4];

  // ---- encoder ----
  ld_res(smem + 0,     g_eWhh0h, 128, by, tid);
  ld_res(smem + 8192,  g_eWhh0l, 128, by, tid);
  ld_res(smem + 16384, g_eWih1h, 128, by, tid);
  ld_res(smem + 24576, g_eWih1l, 128, by, tid);
  ld_res(smem + 32768, g_eWhh1h, 128, by, tid);
  ld_res(smem + 40960, g_eWhh1l, 128, by, tid);
  ld_res(sWst,         g_eWih0h, 16, by, tid);
  ld_res(sWst + 1024,  g_eWih0l, 16, by, tid);
  float4 be0 = bias4(eb0, gh), be1 = bias4(eb1, gh);

  for (int t = 0; t < TIN; ++t) {
    const uint32_t* h0h = g_h0hi[par];
    const uint32_t* h1h = g_h1hi[par];
    {  // L0: x @ Wih0 + h0old @ Whh0
      float a0[4] = {}, a1[4] = {};
      ld_grp<2, false>(rA, rW, g_xhi + (size_t)t * PX, TIN * PX, 0, row0, tid);
      SYNC_ST(2, false);
      ld_grp<8, false>(rA, rW, h0h, PH, 0, row0, tid);
      comp_grp<2>(a0, a1, sA, sWst, sWst + 1024, aoff, boff0, boff1, ks);
      SYNC_ST(8, false);
      ld_grp<8, false>(rA, rW, h0h + 64, PH, 0, row0, tid);
      comp_grp<8>(a0, a1, sA, smem + 0, smem + 8192, aoff, boff0, boff1, ks);
      SYNC_ST(8, false);
      comp_grp<8>(a0, a1, sA, smem + 4096, smem + 12288, aoff, boff0, boff1, ks);
      epilogue(a0, a1, c0r, be0, row0, by, tid, ks, wm, g_, hidT,
               g_h0hi[par ^ 1], nullptr, sbase);
    }
    bt += 16; gbar(bx, bt);
    {  // L1: h1old @ Whh1, then h0new @ Wih1
      const uint32_t* nh = g_h0hi[par ^ 1];
      float a0[4] = {}, a1[4] = {};
      ld_grp<8, false>(rA, rW, h1h, PH, 0, row0, tid);
      SYNC_ST(8, false);
      ld_grp<8, false>(rA, rW, h1h + 64, PH, 0, row0, tid);
      comp_grp<8>(a0, a1, sA, smem + 32768, smem + 40960, aoff, boff0, boff1, ks);
      SYNC_ST(8, false);
      ld_grp<8, false>(rA, rW, nh, PH, 0, row0, tid);
      comp_grp<8>(a0, a1, sA, smem + 36864, smem + 45056, aoff, boff0, boff1, ks);
      SYNC_ST(8, false);
      ld_grp<8, false>(rA, rW, nh + 64, PH, 0, row0, tid);
      comp_grp<8>(a0, a1, sA, smem + 16384, smem + 24576, aoff, boff0, boff1, ks);
      SYNC_ST(8, false);
      comp_grp<8>(a0, a1, sA, smem + 20480, smem + 28672, aoff, boff0, boff1, ks);
      epilogue(a0, a1, c1r, be1, row0, by, tid, ks, wm, g_, hidT,
               g_h1hi[par ^ 1], nullptr, sbase);
    }
    bt += 16; gbar(bx, bt);
    par ^= 1;
  }

  // ---- decoder ----
  ld_res(smem + 0,     g_Wph,    128, by, tid);
  ld_res(smem + 8192,  g_Wpl,    128, by, tid);
  ld_res(smem + 16384, g_dWhh0h, 128, by, tid);
  ld_res(smem + 24576, g_dWhh0l, 128, by, tid);
  ld_res(smem + 32768, g_dWih1h, 128, by, tid);
  ld_res(smem + 40960, g_dWhh1h, 128, by, tid);
  ld_res(sWst,         g_dWih0h, 16, by, tid);
  ld_res(sWst + 1024,  g_dWih0l, 16, by, tid);
  __syncthreads();
  const uint32_t* ih1lo = g_dWih1l + (size_t)by * 64 * PH;
  const uint32_t* hh1lo = g_dWhh1l + (size_t)by * 64 * PH;
  float4 bd0 = bias4(db0, gh), bdp = bias4(g_bp, gh), bd1 = bias4(db1, gh);

  for (int s = 0; s < TOUT; ++s) {
    const uint32_t* h0h = g_h0hi[par];
    const uint32_t* h1h = g_h1hi[par];
    {  // L0
      float a0[4] = {}, a1[4] = {};
      if (s == 0) {
        ld_grp<2, false>(rA, rW, g_xhi + (size_t)(TIN - 1) * PX, TIN * PX, 0,
                         row0, tid);
        SYNC_ST(2, false);
        ld_grp<8, false>(rA, rW, h0h, PH, 0, row0, tid);
        comp_grp<2>(a0, a1, sA, sWst, sWst + 1024, aoff, boff0, boff1, ks);
        SYNC_ST(8, false);
        ld_grp<8, false>(rA, rW, h0h + 64, PH, 0, row0, tid);
        comp_grp<8>(a0, a1, sA, smem + 16384, smem + 24576, aoff, boff0, boff1, ks);
        SYNC_ST(8, false);
        comp_grp<8>(a0, a1, sA, smem + 20480, smem + 28672, aoff, boff0, boff1, ks);
        epilogue(a0, a1, c0r, bd0, row0, by, tid, ks, wm, g_, hidT,
                 g_h0hi[par ^ 1], nullptr, sbase);
      } else {  // h0old @ Whh0 first, then h1 @ Wp
        ld_grp<8, false>(rA, rW, h0h, PH, 0, row0, tid);
        SYNC_ST(8, false);
        ld_grp<8, false>(rA, rW, h0h + 64, PH, 0, row0, tid);
        comp_grp<8>(a0, a1, sA, smem + 16384, smem + 24576, aoff, boff0, boff1, ks);
        SYNC_ST(8, false);
        ld_grp<8, false>(rA, rW, h1h, PH, 0, row0, tid);
        comp_grp<8>(a0, a1, sA, smem + 20480, smem + 28672, aoff, boff0, boff1, ks);
        SYNC_ST(8, false);
        ld_grp<8, false>(rA, rW, h1h + 64, PH, 0, row0, tid);
        comp_grp<8>(a0, a1, sA, smem + 0, smem + 8192, aoff, boff0, boff1, ks);
        SYNC_ST(8, false);
        comp_grp<8>(a0, a1, sA, smem + 4096, smem + 12288, aoff, boff0, boff1, ks);
        epilogue(a0, a1, c0r, bdp, row0, by, tid, ks, wm, g_, hidT,
                 g_h0hi[par ^ 1], nullptr, sbase);
      }
    }
    bt += 16; gbar(bx, bt);
    {  // L1: h1old @ Whh1 (lo streamed), then h0new @ Wih1 (lo streamed)
      const uint32_t* nh = g_h0hi[par ^ 1];
      float a0[4] = {}, a1[4] = {};
      ld_grp<8, true>(rA, rW, h1h, PH, hh1lo, row0, tid);
      SYNC_ST(8, true);
      ld_grp<8, true>(rA, rW, h1h + 64, PH, hh1lo + 64, row0, tid);
      comp_grp<8>(a0, a1, sA, smem + 40960, sWst, aoff, boff0, boff1, ks);
      SYNC_ST(8, true);
      ld_grp<8, true>(rA, rW, nh, PH, ih1lo, row0, tid);
      comp_grp<8>(a0, a1, sA, smem + 45056, sWst, aoff, boff0, boff1, ks);
      SYNC_ST(8, true);
      ld_grp<8, true>(rA, rW, nh + 64, PH, ih1lo + 64, row0, tid);
      comp_grp<8>(a0, a1, sA, smem + 32768, sWst, aoff, boff0, boff1, ks);
      SYNC_ST(8, true);
      comp_grp<8>(a0, a1, sA, smem + 36864, sWst, aoff, boff0, boff1, ks);
      epilogue(a0, a1, c1r, bd1, row0, by, tid, ks, wm, g_, hidT,
               g_h1hi[par ^ 1], g_h1s + (size_t)s * BSZ * HSZ, sbase);
    }
    bt += 16; gbar(bx, bt);
    par ^= 1;
  }
}

// ---------------- final projection ----------------
__global__ __launch_bounds__(256) void out_proj(const float* __restrict__ Wout,
                                                const float* __restrict__ bout,
                                                float* __restrict__ out) {
  __shared__ float hs[32][65];
  __shared__ float wsT[64][36];
  int tid = threadIdx.x;
  int b0 = blockIdx.x * 32, s = blockIdx.y;
  int bloc = tid & 31, f0 = (tid >> 5) * 4;
  float acc[4] = {0.f, 0.f, 0.f, 0.f};
  const float* hsrc = g_h1s + (size_t)s * BSZ * HSZ;
  for (int k0 = 0; k0 < HSZ; k0 += 64) {
    __syncthreads();
#pragma unroll
    for (int qq = 0; qq < 2; ++qq) {
      int idx = tid + qq * 256, row = idx >> 4, kq = idx & 15;
      float4 v = *(const float4*)(hsrc + (size_t)(b0 + row) * HSZ + k0 + kq * 4);
      hs[row][kq * 4 + 0] = v.x; hs[row][kq * 4 + 1] = v.y;
      hs[row][kq * 4 + 2] = v.z; hs[row][kq * 4 + 3] = v.w;
      float4 w = *(const float4*)(Wout + (size_t)row * HSZ + k0 + kq * 4);
      wsT[kq * 4 + 0][row] = w.x; wsT[kq * 4 + 1][row] = w.y;
      wsT[kq * 4 + 2][row] = w.z; wsT[kq * 4 + 3][row] = w.w;
    }
    __syncthreads();
#pragma unroll 8
    for (int kk = 0; kk < 64; ++kk) {
      float hv = hs[bloc][kk];
      float4 w = *(const float4*)&wsT[kk][f0];
      acc[0] += hv * w.x; acc[1] += hv * w.y;
      acc[2] += hv * w.z; acc[3] += hv * w.w;
    }
  }
  float* op = out + (size_t)(b0 + bloc) * TOUT * FSZ + s * FSZ + f0;
  op[0] = acc[0] + bout[f0 + 0];
  op[1] = acc[1] + bout[f0 + 1];
  op[2] = acc[2] + bout[f0 + 2];
  op[3] = acc[3] + bout[f0 + 3];
}

// ---------------- host ----------------
extern "C" void kernel_launch(void* const* d_in, const int* in_sizes, int n_in,
                              void* d_out, int out_size) {
  (void)in_sizes; (void)n_in; (void)out_size;
  const float* x     = (const float*)d_in[0];
  const float* eWih0 = (const float*)d_in[1];
  const float* eWhh0 = (const float*)d_in[2];
  const float* eb0   = (const float*)d_in[3];
  const float* eWih1 = (const float*)d_in[4];
  const float* eWhh1 = (const float*)d_in[5];
  const float* eb1   = (const float*)d_in[6];
  const float* dWih0 = (const float*)d_in[7];
  const float* dWhh0 = (const float*)d_in[8];
  const float* db0   = (const float*)d_in[9];
  const float* dWih1 = (const float*)d_in[10];
  const float* dWhh1 = (const float*)d_in[11];
  const float* db1   = (const float*)d_in[12];
  const float* dWout = (const float*)d_in[13];
  const float* dbout = (const float*)d_in[14];

  void* p;
  cudaGetSymbolAddress(&p, g_Wp);      float* Wp = (float*)p;
  cudaGetSymbolAddress(&p, g_eWih0h);  uint32_t* eWih0h = (uint32_t*)p;
  cudaGetSymbolAddress(&p, g_eWih0l);  uint32_t* eWih0l = (uint32_t*)p;
  cudaGetSymbolAddress(&p, g_eWhh0h);  uint32_t* eWhh0h = (uint32_t*)p;
  cudaGetSymbolAddress(&p, g_eWhh0l);  uint32_t* eWhh0l = (uint32_t*)p;
  cudaGetSymbolAddress(&p, g_eWih1h);  uint32_t* eWih1h = (uint32_t*)p;
  cudaGetSymbolAddress(&p, g_eWih1l);  uint32_t* eWih1l = (uint32_t*)p;
  cudaGetSymbolAddress(&p, g_eWhh1h);  uint32_t* eWhh1h = (uint32_t*)p;
  cudaGetSymbolAddress(&p, g_eWhh1l);  uint32_t* eWhh1l = (uint32_t*)p;
  cudaGetSymbolAddress(&p, g_dWih0h);  uint32_t* dWih0h = (uint32_t*)p;
  cudaGetSymbolAddress(&p, g_dWih0l);  uint32_t* dWih0l = (uint32_t*)p;
  cudaGetSymbolAddress(&p, g_dWhh0h);  uint32_t* dWhh0h = (uint32_t*)p;
  cudaGetSymbolAddress(&p, g_dWhh0l);  uint32_t* dWhh0l = (uint32_t*)p;
  cudaGetSymbolAddress(&p, g_dWih1h);  uint32_t* dWih1h = (uint32_t*)p;
  cudaGetSymbolAddress(&p, g_dWih1l);  uint32_t* dWih1l = (uint32_t*)p;
  cudaGetSymbolAddress(&p, g_dWhh1h);  uint32_t* dWhh1h = (uint32_t*)p;
  cudaGetSymbolAddress(&p, g_dWhh1l);  uint32_t* dWhh1l = (uint32_t*)p;
  cudaGetSymbolAddress(&p, g_Wph);     uint32_t* Wph = (uint32_t*)p;
  cudaGetSymbolAddress(&p, g_Wpl);     uint32_t* Wpl = (uint32_t*)p;

  cudaFuncSetAttribute(lstm_persist, cudaFuncAttributeMaxDynamicSharedMemorySize,
                       SMW * 4);

  zero_init_kernel<<<(BSZ * PH) / 256, 256>>>();
  wp_kernel<<<4 * HSZ, 256>>>(dWih0, dWout);
  bp_kernel<<<(4 * HSZ) / 256, 256>>>(dWih0, db0, dbout);
  pack_x<<<(BSZ * TIN * PX) / 256, 256>>>(x);
  pack_w<<<(1024 * 16) / 256, 256>>>(eWih0, 32, eWih0h, eWih0l);
  pack_w<<<(1024 * 128) / 256, 256>>>(eWhh0, 256, eWhh0h, eWhh0l);
  pack_w<<<(1024 * 128) / 256, 256>>>(eWih1, 256, eWih1h, eWih1l);
  pack_w<<<(1024 * 128) / 256, 256>>>(eWhh1, 256, eWhh1h, eWhh1l);
  pack_w<<<(1024 * 16) / 256, 256>>>(dWih0, 32, dWih0h, dWih0l);
  pack_w<<<(1024 * 128) / 256, 256>>>(dWhh0, 256, dWhh0h, dWhh0l);
  pack_w<<<(1024 * 128) / 256, 256>>>(dWih1, 256, dWih1h, dWih1l);
  pack_w<<<(1024 * 128) / 256, 256>>>(dWhh1, 256, dWhh1h, dWhh1l);
  pack_w<<<(1024 * 128) / 256, 256>>>(Wp, 256, Wph, Wpl);

  lstm_persist<<<NCTA, NTHR, SMW * 4>>>(eb0, eb1, db0, db1);
  out_proj<<<dim3(BSZ / 32, TOUT), 256>>>(dWout, dbout, (float*)d_out);
}

// round 17
// speedup vs baseline: 1.4867x; 1.1104x over previous
#include <cuda_runtime.h>
#include <cuda_bf16.h>
#include <math.h>
#include <stdint.h>

#define BSZ 256
#define HSZ 256
#define TIN 336
#define TOUT 96
#define FSZ 32
#define PH 128
#define PX 16
#define NCTA 128
#define NTHR 512
#define SMW 57344

__device__ uint32_t g_h0hi[2][BSZ * PH];
__device__ uint32_t g_h1hi[2][BSZ * PH];
__device__ uint32_t g_xhi[BSZ * TIN * PX];
__device__ float g_Wp[4 * HSZ * HSZ], g_bp[4 * HSZ];
__device__ float g_h1s[(size_t)TOUT * BSZ * HSZ];
__device__ unsigned g_gbar[8 * 32];

__device__ uint32_t g_eWih0h[1024 * 16],  g_eWih0l[1024 * 16];
__device__ uint32_t g_eWhh0h[1024 * 128], g_eWhh0l[1024 * 128];
__device__ uint32_t g_eWih1h[1024 * 128], g_eWih1l[1024 * 128];
__device__ uint32_t g_eWhh1h[1024 * 128], g_eWhh1l[1024 * 128];
__device__ uint32_t g_dWih0h[1024 * 16],  g_dWih0l[1024 * 16];
__device__ uint32_t g_dWhh0h[1024 * 128], g_dWhh0l[1024 * 128];
__device__ uint32_t g_dWih1h[1024 * 128], g_dWih1l[1024 * 128];
__device__ uint32_t g_dWhh1h[1024 * 128], g_dWhh1l[1024 * 128];
__device__ uint32_t g_Wph[1024 * 128],    g_Wpl[1024 * 128];

__device__ __forceinline__ int j2lp(int j) { return ((j & 1) << 2) | (j >> 1); }

__device__ __forceinline__ void split2(float v0, float v1, uint32_t& hi, uint32_t& lo) {
  __nv_bfloat16 h0 = __float2bfloat16_rn(v0), h1 = __float2bfloat16_rn(v1);
  __nv_bfloat16 l0 = __float2bfloat16_rn(v0 - __bfloat162float(h0));
  __nv_bfloat16 l1 = __float2bfloat16_rn(v1 - __bfloat162float(h1));
  __nv_bfloat162 ph = __nv_bfloat162(h0, h1), pl = __nv_bfloat162(l0, l1);
  hi = *(uint32_t*)&ph;
  lo = *(uint32_t*)&pl;
}

__device__ __forceinline__ uint32_t pack2(float v0, float v1) {
  __nv_bfloat162 ph = __nv_bfloat162(__float2bfloat16_rn(v0), __float2bfloat16_rn(v1));
  return *(uint32_t*)&ph;
}

#define MMA_BF16(C, a0, a1, a2, a3, b0, b1)                                   \
  asm volatile(                                                               \
      "mma.sync.aligned.m16n8k16.row.col.f32.bf16.bf16.f32 "                  \
      "{%0,%1,%2,%3},{%4,%5,%6,%7},{%8,%9},{%0,%1,%2,%3};"                    \
      : "+f"(C[0]), "+f"(C[1]), "+f"(C[2]), "+f"(C[3])                        \
      : "r"(a0), "r"(a1), "r"(a2), "r"(a3), "r"(b0), "r"(b1))

#define LDG_CG2(v, p)                                                         \
  asm volatile("ld.global.cg.v2.u32 {%0,%1},[%2];"                            \
               : "=r"((v).x), "=r"((v).y) : "l"(p))

// ---------------- init / preprocess ----------------
__global__ void zero_init_kernel() {
  int i = blockIdx.x * blockDim.x + threadIdx.x;
  g_h0hi[0][i] = 0u;
  g_h1hi[0][i] = 0u;
  if (i < 256) g_gbar[i] = 0u;
}

__global__ void wp_kernel(const float* __restrict__ Wih0, const float* __restrict__ Wout) {
  __shared__ float wr[FSZ];
  int c = blockIdx.x;
  if (threadIdx.x < FSZ) wr[threadIdx.x] = Wih0[c * FSZ + threadIdx.x];
  __syncthreads();
  int k = threadIdx.x;
  float acc = 0.f;
#pragma unroll
  for (int f = 0; f < FSZ; ++f) acc += wr[f] * Wout[f * HSZ + k];
  g_Wp[c * HSZ + k] = acc;
}

__global__ void bp_kernel(const float* __restrict__ Wih0, const float* __restrict__ b0,
                          const float* __restrict__ bout) {
  int c = blockIdx.x * blockDim.x + threadIdx.x;
  float acc = b0[c];
#pragma unroll
  for (int f = 0; f < FSZ; ++f) acc += Wih0[c * FSZ + f] * bout[f];
  g_bp[c] = acc;
}

__global__ void pack_w(const float* __restrict__ W, int K,
                       uint32_t* __restrict__ ohi, uint32_t* __restrict__ olo) {
  int P = K >> 1;
  int idx = blockIdx.x * 256 + threadIdx.x;
  if (idx >= 1024 * P) return;
  int pr = idx / P, w = idx % P;
  int n = pr & 63, by = pr >> 6;
  int eps = (n >> 3) & 1, qq = (n >> 1) & 3, dlt = n & 1;
  int gate = 2 * eps + dlt;
  int hid = ((n >> 4) << 2) + qq;
  int r = gate * 256 + by * 16 + hid;
  int cch = w >> 3, j = w & 7;
  int k0 = cch * 16 + 2 * j2lp(j);
  split2(W[r * K + k0], W[r * K + k0 + 1], ohi[idx], olo[idx]);
}

__global__ void pack_x(const float* __restrict__ x) {
  int idx = blockIdx.x * 256 + threadIdx.x;
  int w = idx & (PX - 1), bt = idx >> 4;
  int cch = w >> 3, j = w & 7;
  int k0 = cch * 16 + 2 * j2lp(j);
  const float* src = x + (size_t)bt * FSZ + k0;
  g_xhi[idx] = pack2(src[0], src[1]);
}

// ---------------- persistent building blocks ----------------
__device__ __forceinline__ void gbar(int grp, unsigned target) {
  __syncthreads();
  __threadfence();
  if (threadIdx.x == 0) {
    unsigned old = atomicAdd(&g_gbar[grp * 32], 1u);
    if (old + 1u < target) {
      volatile unsigned* p = &g_gbar[grp * 32];
      while (*p < target) {}
    }
  }
  __syncthreads();
}

__device__ __forceinline__ void ld_res(uint32_t* dst, const uint32_t* src,
                                       int P, int by, int tid) {
  const uint32_t* s = src + (size_t)(by * 64) * P;
  for (int idx = tid * 2; idx < 64 * P; idx += 1024) {
    int rw = idx / P, w = idx - rw * P;
    int c = w >> 3, j = w & 7;
    uint2 v = *(const uint2*)(s + (size_t)rw * P + w);
    *(uint2*)&dst[c * 512 + rw * 8 + j] = v;
  }
}

template <int GC, bool SW>
__device__ __forceinline__ void ld_grp(uint2* rA, uint2* rW,
    const uint32_t* __restrict__ ahi, int lda,
    const uint32_t* __restrict__ gwl, int row0, int tid) {
  constexpr int ITS = (GC + 3) / 4;
#pragma unroll
  for (int it = 0; it < ITS; ++it) {
    int idx = tid * 2 + it * 1024;
    if (GC >= 4 || idx < GC * 256) {
      int rw = (idx & 255) >> 3, j = idx & 7, c = idx >> 8;
      size_t go = (size_t)(row0 + rw) * lda + (c << 3) + j;
      LDG_CG2(rA[it], ahi + go);
    }
  }
  if (SW) {
#pragma unroll
    for (int it = 0; it < (GC + 1) / 2; ++it) {
      int idx = tid * 2 + it * 1024;
      int rw = (idx & 511) >> 3, j = idx & 7, c = idx >> 9;
      LDG_CG2(rW[it], gwl + rw * PH + (c << 3) + j);
    }
  }
}

template <int GC, bool SW>
__device__ __forceinline__ void st_grp(const uint2* rA, const uint2* rW,
                                       uint32_t* sAb, uint32_t* sWst, int tid) {
  constexpr int ITS = (GC + 3) / 4;
#pragma unroll
  for (int it = 0; it < ITS; ++it) {
    int idx = tid * 2 + it * 1024;
    if (GC >= 4 || idx < GC * 256) *(uint2*)&sAb[idx] = rA[it];
  }
  if (SW) {
#pragma unroll
    for (int it = 0; it < (GC + 1) / 2; ++it)
      *(uint2*)&sWst[tid * 2 + it * 1024] = rW[it];
  }
}

// bf16x2: A-hi x (W-hi + W-lo) -> 4 MMAs per chunk-position
template <int GC>
__device__ __forceinline__ void comp_grp(float* a0, float* a1,
    const uint32_t* sAb, const uint32_t* swh, const uint32_t* swl,
    int aoff, int boff0, int boff1, int ks) {
  int cb = ks * (GC >> 1);
#pragma unroll
  for (int ci = 0; ci < (GC >> 1); ++ci) {
    int c = cb + ci;
    const uint32_t* bAh = sAb + (c << 8);
    const uint32_t* bWh = swh + (c << 9);
    const uint32_t* bWl = swl + (c << 9);
    uint2 Ah0 = *(const uint2*)(bAh + aoff), Ah1 = *(const uint2*)(bAh + aoff + 64);
    uint2 Bh0 = *(const uint2*)(bWh + boff0), Bl0 = *(const uint2*)(bWl + boff0);
    uint2 Bh1 = *(const uint2*)(bWh + boff1), Bl1 = *(const uint2*)(bWl + boff1);
    MMA_BF16(a0, Ah0.x, Ah1.x, Ah0.y, Ah1.y, Bh0.x, Bh0.y);
    MMA_BF16(a0, Ah0.x, Ah1.x, Ah0.y, Ah1.y, Bl0.x, Bl0.y);
    MMA_BF16(a1, Ah0.x, Ah1.x, Ah0.y, Ah1.y, Bh1.x, Bh1.y);
    MMA_BF16(a1, Ah0.x, Ah1.x, Ah0.y, Ah1.y, Bl1.x, Bl1.y);
  }
}

// k-split reduce + register-resident pointwise; h packed as plain bf16 pairs
__device__ __forceinline__ void epilogue(
    float* a0, float* a1, float* creg, float4 bu,
    int row0, int by, int tid, int ks, int wm, int g_, int hidT,
    uint32_t* __restrict__ outHi, float* __restrict__ outF, float* sbase) {
  float* psum = sbase;          // buf0 region
  float* hbuf = sbase + 2048;   // buf1 region
  __syncthreads();
  if (ks) {
    float4* p = (float4*)(psum + (tid - 256) * 8);
    p[0] = make_float4(a0[0], a0[1], a0[2], a0[3]);
    p[1] = make_float4(a1[0], a1[1], a1[2], a1[3]);
  }
  __syncthreads();
  if (!ks) {
    const float4* p = (const float4*)(psum + tid * 8);
    float4 p0 = p[0], p1 = p[1];
    a0[0] += p0.x; a0[1] += p0.y; a0[2] += p0.z; a0[3] += p0.w;
    a1[0] += p1.x; a1[1] += p1.y; a1[2] += p1.z; a1[3] += p1.w;
#pragma unroll
    for (int uu = 0; uu < 2; ++uu) {
      int row = wm + g_ + 8 * uu;
      float gi = (uu ? a0[2] : a0[0]) + bu.x;
      float gf = (uu ? a0[3] : a0[1]) + bu.y;
      float gg = (uu ? a1[2] : a1[0]) + bu.z;
      float go = (uu ? a1[3] : a1[1]) + bu.w;
      float si = 1.f / (1.f + expf(-gi));
      float sf = 1.f / (1.f + expf(-gf));
      float so = 1.f / (1.f + expf(-go));
      float cn = sf * creg[uu] + si * tanhf(gg);
      float hn = so * tanhf(cn);
      creg[uu] = cn;
      hbuf[row * 17 + hidT] = hn;
      if (outF) outF[(size_t)(row0 + row) * HSZ + by * 16 + hidT] = hn;
    }
  }
  __syncthreads();
  if (tid < 256) {
    int pr = tid >> 3, jj = tid & 7, lp = j2lp(jj);
    size_t o = (size_t)(row0 + pr) * PH + by * 8 + jj;
    outHi[o] = pack2(hbuf[pr * 17 + 2 * lp], hbuf[pr * 17 + 2 * lp + 1]);
  }
}

__device__ __forceinline__ float4 bias4(const float* b, int gh) {
  return make_float4(b[gh], b[HSZ + gh], b[2 * HSZ + gh], b[3 * HSZ + gh]);
}

// single-sync staged group (double-buffered A): st into BUF, one sync
#define ST1(GC, BUF)                                                          \
  do {                                                                        \
    st_grp<GC, false>(rA, rW, sA + (BUF) * 2048, sWst, tid);                  \
    __syncthreads();                                                          \
  } while (0)

// streamed-W group (decoder L1): keep 2-sync protection, fixed buf0 + sWst
#define SYNC_ST_SW(GC)                                                        \
  __syncthreads();                                                            \
  st_grp<GC, true>(rA, rW, sA, sWst, tid);                                    \
  __syncthreads()

// ---------------- persistent kernel ----------------
__global__ __launch_bounds__(NTHR) void lstm_persist(
    const float* __restrict__ eb0, const float* __restrict__ eb1,
    const float* __restrict__ db0, const float* __restrict__ db1) {
  extern __shared__ uint32_t smem[];
  int tid = threadIdx.x;
  int bx = blockIdx.x & 7, by = blockIdx.x >> 3;
  int row0 = bx * 32;
  int lane = tid & 31, wid = tid >> 5, g_ = lane >> 2, q = lane & 3;
  int ks = wid >> 3, wpos = wid & 7;
  int wm = (wpos & 1) * 16, wn = (wpos >> 1) * 16;
  int hidT = (wn >> 2) + q;
  int aoff = (wm + g_) * 8 + 2 * q;
  int boff0 = (wn + g_) * 8 + 2 * q, boff1 = (wn + 8 + g_) * 8 + 2 * q;
  uint32_t* sA = smem + 49152;
  uint32_t* sWst = smem + 53248;
  float* sbase = (float*)sA;
  int gh = by * 16 + hidT;
  float c0r[2] = {0.f, 0.f}, c1r[2] = {0.f, 0.f};
  unsigned bt = 0;
  int par = 0;
  uint2 rA[2], rW[4];

  // ---- encoder ----
  ld_res(smem + 0,     g_eWhh0h, 128, by, tid);
  ld_res(smem + 8192,  g_eWhh0l, 128, by, tid);
  ld_res(smem + 16384, g_eWih1h, 128, by, tid);
  ld_res(smem + 24576, g_eWih1l, 128, by, tid);
  ld_res(smem + 32768, g_eWhh1h, 128, by, tid);
  ld_res(smem + 40960, g_eWhh1l, 128, by, tid);
  ld_res(sWst,         g_eWih0h, 16, by, tid);
  ld_res(sWst + 1024,  g_eWih0l, 16, by, tid);
  float4 be0 = bias4(eb0, gh), be1 = bias4(eb1, gh);

  for (int t = 0; t < TIN; ++t) {
    const uint32_t* h0h = g_h0hi[par];
    const uint32_t* h1h = g_h1hi[par];
    {  // L0: x @ Wih0 + h0old @ Whh0   (buffers 0,1,0)
      float a0[4] = {}, a1[4] = {};
      ld_grp<2, false>(rA, rW, g_xhi + (size_t)t * PX, TIN * PX, 0, row0, tid);
      ST1(2, 0);
      ld_grp<8, false>(rA, rW, h0h, PH, 0, row0, tid);
      comp_grp<2>(a0, a1, sA, sWst, sWst + 1024, aoff, boff0, boff1, ks);
      ST1(8, 1);
      ld_grp<8, false>(rA, rW, h0h + 64, PH, 0, row0, tid);
      comp_grp<8>(a0, a1, sA + 2048, smem + 0, smem + 8192, aoff, boff0, boff1, ks);
      ST1(8, 0);
      comp_grp<8>(a0, a1, sA, smem + 4096, smem + 12288, aoff, boff0, boff1, ks);
      epilogue(a0, a1, c0r, be0, row0, by, tid, ks, wm, g_, hidT,
               g_h0hi[par ^ 1], nullptr, sbase);
    }
    bt += 16; gbar(bx, bt);   // single barrier per encoder timestep
    {  // L1: h1old @ Whh1, then h0new @ Wih1   (buffers 1,0,1,0)
      const uint32_t* nh = g_h0hi[par ^ 1];
      float a0[4] = {}, a1[4] = {};
      ld_grp<8, false>(rA, rW, h1h, PH, 0, row0, tid);
      ST1(8, 1);
      ld_grp<8, false>(rA, rW, h1h + 64, PH, 0, row0, tid);
      comp_grp<8>(a0, a1, sA + 2048, smem + 32768, smem + 40960, aoff, boff0, boff1, ks);
      ST1(8, 0);
      ld_grp<8, false>(rA, rW, nh, PH, 0, row0, tid);
      comp_grp<8>(a0, a1, sA, smem + 36864, smem + 45056, aoff, boff0, boff1, ks);
      ST1(8, 1);
      ld_grp<8, false>(rA, rW, nh + 64, PH, 0, row0, tid);
      comp_grp<8>(a0, a1, sA + 2048, smem + 16384, smem + 24576, aoff, boff0, boff1, ks);
      ST1(8, 0);
      comp_grp<8>(a0, a1, sA, smem + 20480, smem + 28672, aoff, boff0, boff1, ks);
      epilogue(a0, a1, c1r, be1, row0, by, tid, ks, wm, g_, hidT,
               g_h1hi[par ^ 1], nullptr, sbase);
    }
    par ^= 1;
  }

  // ---- decoder ----
  ld_res(smem + 0,     g_Wph,    128, by, tid);
  ld_res(smem + 8192,  g_Wpl,    128, by, tid);
  ld_res(smem + 16384, g_dWhh0h, 128, by, tid);
  ld_res(smem + 24576, g_dWhh0l, 128, by, tid);
  ld_res(smem + 32768, g_dWih1h, 128, by, tid);
  ld_res(smem + 40960, g_dWhh1h, 128, by, tid);
  ld_res(sWst,         g_dWih0h, 16, by, tid);
  ld_res(sWst + 1024,  g_dWih0l, 16, by, tid);
  __syncthreads();
  const uint32_t* ih1lo = g_dWih1l + (size_t)by * 64 * PH;
  const uint32_t* hh1lo = g_dWhh1l + (size_t)by * 64 * PH;
  float4 bd0 = bias4(db0, gh), bdp = bias4(g_bp, gh), bd1 = bias4(db1, gh);

  for (int s = 0; s < TOUT; ++s) {
    const uint32_t* h0h = g_h0hi[par];
    const uint32_t* h1h = g_h1hi[par];
    {  // L0
      float a0[4] = {}, a1[4] = {};
      if (s == 0) {  // buffers 0,1,0
        ld_grp<2, false>(rA, rW, g_xhi + (size_t)(TIN - 1) * PX, TIN * PX, 0,
                         row0, tid);
        ST1(2, 0);
        ld_grp<8, false>(rA, rW, h0h, PH, 0, row0, tid);
        comp_grp<2>(a0, a1, sA, sWst, sWst + 1024, aoff, boff0, boff1, ks);
        ST1(8, 1);
        ld_grp<8, false>(rA, rW, h0h + 64, PH, 0, row0, tid);
        comp_grp<8>(a0, a1, sA + 2048, smem + 16384, smem + 24576, aoff, boff0, boff1, ks);
        ST1(8, 0);
        comp_grp<8>(a0, a1, sA, smem + 20480, smem + 28672, aoff, boff0, boff1, ks);
        epilogue(a0, a1, c0r, bd0, row0, by, tid, ks, wm, g_, hidT,
                 g_h0hi[par ^ 1], nullptr, sbase);
      } else {  // h0old @ Whh0, then h1 @ Wp   (buffers 0,1,0,1)
        ld_grp<8, false>(rA, rW, h0h, PH, 0, row0, tid);
        ST1(8, 0);
        ld_grp<8, false>(rA, rW, h0h + 64, PH, 0, row0, tid);
        comp_grp<8>(a0, a1, sA, smem + 16384, smem + 24576, aoff, boff0, boff1, ks);
        ST1(8, 1);
        ld_grp<8, false>(rA, rW, h1h, PH, 0, row0, tid);
        comp_grp<8>(a0, a1, sA + 2048, smem + 20480, smem + 28672, aoff, boff0, boff1, ks);
        ST1(8, 0);
        ld_grp<8, false>(rA, rW, h1h + 64, PH, 0, row0, tid);
        comp_grp<8>(a0, a1, sA, smem + 0, smem + 8192, aoff, boff0, boff1, ks);
        ST1(8, 1);
        comp_grp<8>(a0, a1, sA + 2048, smem + 4096, smem + 12288, aoff, boff0, boff1, ks);
        epilogue(a0, a1, c0r, bdp, row0, by, tid, ks, wm, g_, hidT,
                 g_h0hi[par ^ 1], nullptr, sbase);
      }
    }
    bt += 16; gbar(bx, bt);
    {  // L1: h1old @ Whh1 (lo streamed), then h0new @ Wih1 (lo streamed)
      const uint32_t* nh = g_h0hi[par ^ 1];
      float a0[4] = {}, a1[4] = {};
      ld_grp<8, true>(rA, rW, h1h, PH, hh1lo, row0, tid);
      SYNC_ST_SW(8);
      ld_grp<8, true>(rA, rW, h1h + 64, PH, hh1lo + 64, row0, tid);
      comp_grp<8>(a0, a1, sA, smem + 40960, sWst, aoff, boff0, boff1, ks);
      SYNC_ST_SW(8);
      ld_grp<8, true>(rA, rW, nh, PH, ih1lo, row0, tid);
      comp_grp<8>(a0, a1, sA, smem + 45056, sWst, aoff, boff0, boff1, ks);
      SYNC_ST_SW(8);
      ld_grp<8, true>(rA, rW, nh + 64, PH, ih1lo + 64, row0, tid);
      comp_grp<8>(a0, a1, sA, smem + 32768, sWst, aoff, boff0, boff1, ks);
      SYNC_ST_SW(8);
      comp_grp<8>(a0, a1, sA, smem + 36864, sWst, aoff, boff0, boff1, ks);
      epilogue(a0, a1, c1r, bd1, row0, by, tid, ks, wm, g_, hidT,
               g_h1hi[par ^ 1], g_h1s + (size_t)s * BSZ * HSZ, sbase);
    }
    bt += 16; gbar(bx, bt);
    par ^= 1;
  }
}

// ---------------- final projection ----------------
__global__ __launch_bounds__(256) void out_proj(const float* __restrict__ Wout,
                                                const float* __restrict__ bout,
                                                float* __restrict__ out) {
  __shared__ float hs[32][65];
  __shared__ float wsT[64][36];
  int tid = threadIdx.x;
  int b0 = blockIdx.x * 32, s = blockIdx.y;
  int bloc = tid & 31, f0 = (tid >> 5) * 4;
  float acc[4] = {0.f, 0.f, 0.f, 0.f};
  const float* hsrc = g_h1s + (size_t)s * BSZ * HSZ;
  for (int k0 = 0; k0 < HSZ; k0 += 64) {
    __syncthreads();
#pragma unroll
    for (int qq = 0; qq < 2; ++qq) {
      int idx = tid + qq * 256, row = idx >> 4, kq = idx & 15;
      float4 v = *(const float4*)(hsrc + (size_t)(b0 + row) * HSZ + k0 + kq * 4);
      hs[row][kq * 4 + 0] = v.x; hs[row][kq * 4 + 1] = v.y;
      hs[row][kq * 4 + 2] = v.z; hs[row][kq * 4 + 3] = v.w;
      float4 w = *(const float4*)(Wout + (size_t)row * HSZ + k0 + kq * 4);
      wsT[kq * 4 + 0][row] = w.x; wsT[kq * 4 + 1][row] = w.y;
      wsT[kq * 4 + 2][row] = w.z; wsT[kq * 4 + 3][row] = w.w;
    }
    __syncthreads();
#pragma unroll 8
    for (int kk = 0; kk < 64; ++kk) {
      float hv = hs[bloc][kk];
      float4 w = *(const float4*)&wsT[kk][f0];
      acc[0] += hv * w.x; acc[1] += hv * w.y;
      acc[2] += hv * w.z; acc[3] += hv * w.w;
    }
  }
  float* op = out + (size_t)(b0 + bloc) * TOUT * FSZ + s * FSZ + f0;
  op[0] = acc[0] + bout[f0 + 0];
  op[1] = acc[1] + bout[f0 + 1];
  op[2] = acc[2] + bout[f0 + 2];
  op[3] = acc[3] + bout[f0 + 3];
}

// ---------------- host ----------------
extern "C" void kernel_launch(void* const* d_in, const int* in_sizes, int n_in,
                              void* d_out, int out_size) {
  (void)in_sizes; (void)n_in; (void)out_size;
  const float* x     = (const float*)d_in[0];
  const float* eWih0 = (const float*)d_in[1];
  const float* eWhh0 = (const float*)d_in[2];
  const float* eb0   = (const float*)d_in[3];
  const float* eWih1 = (const float*)d_in[4];
  const float* eWhh1 = (const float*)d_in[5];
  const float* eb1   = (const float*)d_in[6];
  const float* dWih0 = (const float*)d_in[7];
  const float* dWhh0 = (const float*)d_in[8];
  const float* db0   = (const float*)d_in[9];
  const float* dWih1 = (const float*)d_in[10];
  const float* dWhh1 = (const float*)d_in[11];
  const float* db1   = (const float*)d_in[12];
  const float* dWout = (const float*)d_in[13];
  const float* dbout = (const float*)d_in[14];

  void* p;
  cudaGetSymbolAddress(&p, g_Wp);      float* Wp = (float*)p;
  cudaGetSymbolAddress(&p, g_eWih0h);  uint32_t* eWih0h = (uint32_t*)p;
  cudaGetSymbolAddress(&p, g_eWih0l);  uint32_t* eWih0l = (uint32_t*)p;
  cudaGetSymbolAddress(&p, g_eWhh0h);  uint32_t* eWhh0h = (uint32_t*)p;
  cudaGetSymbolAddress(&p, g_eWhh0l);  uint32_t* eWhh0l = (uint32_t*)p;
  cudaGetSymbolAddress(&p, g_eWih1h);  uint32_t* eWih1h = (uint32_t*)p;
  cudaGetSymbolAddress(&p, g_eWih1l);  uint32_t* eWih1l = (uint32_t*)p;
  cudaGetSymbolAddress(&p, g_eWhh1h);  uint32_t* eWhh1h = (uint32_t*)p;
  cudaGetSymbolAddress(&p, g_eWhh1l);  uint32_t* eWhh1l = (uint32_t*)p;
  cudaGetSymbolAddress(&p, g_dWih0h);  uint32_t* dWih0h = (uint32_t*)p;
  cudaGetSymbolAddress(&p, g_dWih0l);  uint32_t* dWih0l = (uint32_t*)p;
  cudaGetSymbolAddress(&p, g_dWhh0h);  uint32_t* dWhh0h = (uint32_t*)p;
  cudaGetSymbolAddress(&p, g_dWhh0l);  uint32_t* dWhh0l = (uint32_t*)p;
  cudaGetSymbolAddress(&p, g_dWih1h);  uint32_t* dWih1h = (uint32_t*)p;
  cudaGetSymbolAddress(&p, g_dWih1l);  uint32_t* dWih1l = (uint32_t*)p;
  cudaGetSymbolAddress(&p, g_dWhh1h);  uint32_t* dWhh1h = (uint32_t*)p;
  cudaGetSymbolAddress(&p, g_dWhh1l);  uint32_t* dWhh1l = (uint32_t*)p;
  cudaGetSymbolAddress(&p, g_Wph);     uint32_t* Wph = (uint32_t*)p;
  cudaGetSymbolAddress(&p, g_Wpl);     uint32_t* Wpl = (uint32_t*)p;

  cudaFuncSetAttribute(lstm_persist, cudaFuncAttributeMaxDynamicSharedMemorySize,
                       SMW * 4);

  zero_init_kernel<<<(BSZ * PH) / 256, 256>>>();
  wp_kernel<<<4 * HSZ, 256>>>(dWih0, dWout);
  bp_kernel<<<(4 * HSZ) / 256, 256>>>(dWih0, db0, dbout);
  pack_x<<<(BSZ * TIN * PX) / 256, 256>>>(x);
  pack_w<<<(1024 * 16) / 256, 256>>>(eWih0, 32, eWih0h, eWih0l);
  pack_w<<<(1024 * 128) / 256, 256>>>(eWhh0, 256, eWhh0h, eWhh0l);
  pack_w<<<(1024 * 128) / 256, 256>>>(eWih1, 256, eWih1h, eWih1l);
  pack_w<<<(1024 * 128) / 256, 256>>>(eWhh1, 256, eWhh1h, eWhh1l);
  pack_w<<<(1024 * 16) / 256, 256>>>(dWih0, 32, dWih0h, dWih0l);
  pack_w<<<(1024 * 128) / 256, 256>>>(dWhh0, 256, dWhh0h, dWhh0l);
  pack_w<<<(1024 * 128) / 256, 256>>>(dWih1, 256, dWih1h, dWih1l);
  pack_w<<<(1024 * 128) / 256, 256>>>(dWhh1, 256, dWhh1h, dWhh1l);
  pack_w<<<(1024 * 128) / 256, 256>>>(Wp, 256, Wph, Wpl);

  lstm_persist<<<NCTA, NTHR, SMW * 4>>>(eb0, eb1, db0, db1);
  out_proj<<<dim3(BSZ / 32, TOUT), 256>>>(dWout, dbout, (float*)d_out);
}